// round 1
// baseline (speedup 1.0000x reference)
#include <cuda_runtime.h>
#include <cstdint>
#include <cstdio>

typedef unsigned long long u64;

// ---------------- packed fp32x2 helpers (sm_100+ fma.rn.f32x2) ----------------
__device__ __forceinline__ u64 pack2(float x, float y) {
    u64 r; asm("mov.b64 %0, {%1, %2};" : "=l"(r) : "f"(x), "f"(y)); return r;
}
__device__ __forceinline__ float2 unpack2(u64 v) {
    float2 r; asm("mov.b64 {%0, %1}, %2;" : "=f"(r.x), "=f"(r.y) : "l"(v)); return r;
}
__device__ __forceinline__ void fma2(u64& d, u64 a, u64 b) {
    asm("fma.rn.f32x2 %0, %1, %2, %0;" : "+l"(d) : "l"(a), "l"(b));
}
__device__ __forceinline__ u64 mul2(u64 a, u64 b) {
    u64 d; asm("mul.rn.f32x2 %0, %1, %2;" : "=l"(d) : "l"(a), "l"(b)); return d;
}

// ---------------- scratch (device globals: allocation-free) ----------------
__device__ float g_Qt[4096 * 1024];
__device__ float g_Qd[4096 * 1024];
__device__ float g_Kt[1024 * 1024];
__device__ float g_Vt[1024 * 1024];
__device__ float g_Kd[1024 * 1024];
__device__ float g_Vd[1024 * 1024];
__device__ float g_Ct[4096 * 1024];
__device__ float g_Cd[4096 * 1024];
__device__ float g_H [4096 * 1024];
__device__ float g_gate[4096];

// ---------------- generic tiled SGEMM: C(MxN) = A(MxK) @ B(KxN) (+epilogues) --
// EPI 0: C = AB + bias
// EPI 2: C = relu(C + AB)           (bias unused)
// EPI 3: C = C + gate[r]*(AB + bias - C)   (lerp blend)
template<int EPI>
__global__ __launch_bounds__(256)
void sgemm(const float* __restrict__ A, const float* __restrict__ B,
           const float* __restrict__ bias, float* __restrict__ C,
           int M, int N, int K, const float* __restrict__ gate)
{
    __shared__ float As[8][128];
    __shared__ float Bs[8][128];
    const int tid  = threadIdx.x;
    const int row0 = blockIdx.y * 128;
    const int col0 = blockIdx.x * 128;
    const int tx   = tid & 15;
    const int ty   = tid >> 4;
    const int aRow = tid >> 1;
    const int aK   = (tid & 1) * 4;
    const int bRow = tid >> 5;
    const int bCol = (tid & 31) * 4;

    u64 acc2[8][4] = {};

    const bool aValid = (row0 + aRow) < M;
    const float* Aptr = A + (size_t)(row0 + aRow) * K + aK;
    const float* Bptr = B + (size_t)bRow * N + col0 + bCol;

    for (int k0 = 0; k0 < K; k0 += 8) {
        float4 av = make_float4(0.f, 0.f, 0.f, 0.f);
        if (aValid) av = *(const float4*)(Aptr + k0);
        As[aK + 0][aRow] = av.x; As[aK + 1][aRow] = av.y;
        As[aK + 2][aRow] = av.z; As[aK + 3][aRow] = av.w;
        *(float4*)&Bs[bRow][bCol] = *(const float4*)(Bptr + (size_t)k0 * N);
        __syncthreads();
        #pragma unroll
        for (int kk = 0; kk < 8; kk++) {
            u64 b2[4];
            const u64* bp = (const u64*)&Bs[kk][tx * 8];
            #pragma unroll
            for (int j = 0; j < 4; j++) b2[j] = bp[j];
            #pragma unroll
            for (int i = 0; i < 8; i++) {
                float a = As[kk][ty * 8 + i];
                u64 ad = pack2(a, a);
                #pragma unroll
                for (int j = 0; j < 4; j++) fma2(acc2[i][j], ad, b2[j]);
            }
        }
        __syncthreads();
    }

    #pragma unroll
    for (int i = 0; i < 8; i++) {
        int r = row0 + ty * 8 + i;
        if (r >= M) continue;
        float gg = 0.f;
        if (EPI == 3) gg = gate[r];
        #pragma unroll
        for (int j = 0; j < 4; j++) {
            int c = col0 + tx * 8 + j * 2;
            size_t idx = (size_t)r * N + c;
            float2 v = unpack2(acc2[i][j]);
            if (EPI == 0) {
                C[idx]     = v.x + bias[c];
                C[idx + 1] = v.y + bias[c + 1];
            } else if (EPI == 2) {
                C[idx]     = fmaxf(C[idx]     + v.x, 0.f);
                C[idx + 1] = fmaxf(C[idx + 1] + v.y, 0.f);
            } else {
                float s0 = v.x + bias[c];
                float s1 = v.y + bias[c + 1];
                float o0 = C[idx], o1 = C[idx + 1];
                C[idx]     = o0 + gg * (s0 - o0);
                C[idx + 1] = o1 + gg * (s1 - o1);
            }
        }
    }
}

// ---------------- flash attention: 1 thread per query row, online softmax ----
// Q: (B*L, 1024) with head h at cols [h*64, h*64+64); K,V: (S, 1024) same layout.
// O: (B*L, 1024). Grid (L/64, H, B), block 64.
__global__ __launch_bounds__(64)
void flash_attn(const float* __restrict__ Q, const float* __restrict__ Kb,
                const float* __restrict__ Vb, float* __restrict__ O, int S)
{
    __shared__ u64 Ks[64 * 32];     // 16 KB
    __shared__ u64 Vs[64 * 32];     // 16 KB
    __shared__ float Ss[64 * 64];   // 16 KB  (scores: [j][tid])
    const int tid = threadIdx.x;
    const int h   = blockIdx.y;
    const int b   = blockIdx.z;
    const int row = b * 512 + blockIdx.x * 64 + tid;

    const u64* qp = (const u64*)(Q + (size_t)row * 1024 + h * 64);
    u64 q2[32];
    #pragma unroll
    for (int i = 0; i < 32; i++) q2[i] = qp[i];

    u64 acc2[32] = {};
    float m = -1e30f, lsum = 0.f;
    const float scale = 0.125f;  // 1/sqrt(64)

    for (int s0 = 0; s0 < S; s0 += 64) {
        int jmax = S - s0; if (jmax > 64) jmax = 64;
        // cooperative K/V tile load (coalesced 256B per warp)
        #pragma unroll
        for (int i = 0; i < 32; i++) {
            int idx = i * 64 + tid;
            int j = idx >> 5, e2 = idx & 31;
            int srow = s0 + j;
            u64 kv = 0, vv = 0;
            if (srow < S) {
                kv = ((const u64*)(Kb + (size_t)srow * 1024 + h * 64))[e2];
                vv = ((const u64*)(Vb + (size_t)srow * 1024 + h * 64))[e2];
            }
            Ks[idx] = kv; Vs[idx] = vv;
        }
        __syncthreads();

        float tmax = -1e30f;
        for (int j = 0; j < 64; j++) {
            float s;
            if (j < jmax) {
                u64 s2 = 0;
                #pragma unroll
                for (int e = 0; e < 32; e++) fma2(s2, q2[e], Ks[j * 32 + e]);
                float2 sf = unpack2(s2);
                s = (sf.x + sf.y) * scale;
            } else {
                s = -1e30f;
            }
            tmax = fmaxf(tmax, s);
            Ss[j * 64 + tid] = s;
        }

        float mnew  = fmaxf(m, tmax);
        float alpha = __expf(m - mnew);
        lsum *= alpha;
        u64 a2 = pack2(alpha, alpha);
        #pragma unroll
        for (int e = 0; e < 32; e++) acc2[e] = mul2(acc2[e], a2);

        for (int j = 0; j < 64; j++) {
            float p = __expf(Ss[j * 64 + tid] - mnew);
            lsum += p;
            u64 p2 = pack2(p, p);
            #pragma unroll
            for (int e = 0; e < 32; e++) fma2(acc2[e], p2, Vs[j * 32 + e]);
        }
        m = mnew;
        __syncthreads();
    }

    float inv = 1.f / lsum;
    float2* op = (float2*)(O + (size_t)row * 1024 + h * 64);
    #pragma unroll
    for (int e = 0; e < 32; e++) {
        float2 v = unpack2(acc2[e]);
        v.x *= inv; v.y *= inv;
        op[e] = v;
    }
}

// ---------------- gate: G[r] = sigmoid(H[r,:] . W2 + b2), one warp per row ----
__global__ __launch_bounds__(256)
void gate_kernel(const float* __restrict__ H, const float* __restrict__ W2,
                 const float* __restrict__ b2, float* __restrict__ G)
{
    int w = (blockIdx.x * blockDim.x + threadIdx.x) >> 5;
    int lane = threadIdx.x & 31;
    const float* hp = H + (size_t)w * 1024;
    float s = 0.f;
    #pragma unroll
    for (int i = 0; i < 32; i++) s += hp[lane + i * 32] * W2[lane + i * 32];
    #pragma unroll
    for (int o = 16; o; o >>= 1) s += __shfl_xor_sync(0xffffffffu, s, o);
    if (lane == 0) G[w] = 1.f / (1.f + __expf(-(s + b2[0])));
}

// ---------------- launch ----------------
extern "C" void kernel_launch(void* const* d_in, const int* in_sizes, int n_in,
                              void* d_out, int out_size)
{
    const float* trend  = (const float*)d_in[0];
    const float* detail = (const float*)d_in[1];
    const float* protoT = (const float*)d_in[2];
    const float* protoD = (const float*)d_in[3];
    const float* tWq = (const float*)d_in[4];  const float* tbq = (const float*)d_in[5];
    const float* tWk = (const float*)d_in[6];  const float* tbk = (const float*)d_in[7];
    const float* tWv = (const float*)d_in[8];  const float* tbv = (const float*)d_in[9];
    const float* tWo = (const float*)d_in[10]; const float* tbo = (const float*)d_in[11];
    const float* dWq = (const float*)d_in[12]; const float* dbq = (const float*)d_in[13];
    const float* dWk = (const float*)d_in[14]; const float* dbk = (const float*)d_in[15];
    const float* dWv = (const float*)d_in[16]; const float* dbv = (const float*)d_in[17];
    const float* dWo = (const float*)d_in[18]; const float* dbo = (const float*)d_in[19];
    const float* gW1 = (const float*)d_in[20]; const float* gb1 = (const float*)d_in[21];
    const float* gW2 = (const float*)d_in[22]; const float* gb2 = (const float*)d_in[23];
    float* out = (float*)d_out;

    float *Qt, *Qd, *Kt, *Vt, *Kd, *Vd, *Ct, *Cd, *H, *G;
    cudaGetSymbolAddress((void**)&Qt, g_Qt);
    cudaGetSymbolAddress((void**)&Qd, g_Qd);
    cudaGetSymbolAddress((void**)&Kt, g_Kt);
    cudaGetSymbolAddress((void**)&Vt, g_Vt);
    cudaGetSymbolAddress((void**)&Kd, g_Kd);
    cudaGetSymbolAddress((void**)&Vd, g_Vd);
    cudaGetSymbolAddress((void**)&Ct, g_Ct);
    cudaGetSymbolAddress((void**)&Cd, g_Cd);
    cudaGetSymbolAddress((void**)&H,  g_H);
    cudaGetSymbolAddress((void**)&G,  g_gate);

    const dim3 blk(256);

    // Q projections: (4096,1024) = emb(4096,1024) @ Wq(1024,1024) + bq
    sgemm<0><<<dim3(8, 32), blk>>>(trend,  tWq, tbq, Qt, 4096, 1024, 1024, nullptr);
    sgemm<0><<<dim3(8, 32), blk>>>(detail, dWq, dbq, Qd, 4096, 1024, 1024, nullptr);

    // K/V projections: (1000,1024) = protos(1000,4096) @ W(4096,1024) + b
    sgemm<0><<<dim3(8, 8), blk>>>(protoT, tWk, tbk, Kt, 1000, 1024, 4096, nullptr);
    sgemm<0><<<dim3(8, 8), blk>>>(protoT, tWv, tbv, Vt, 1000, 1024, 4096, nullptr);
    sgemm<0><<<dim3(8, 8), blk>>>(protoD, dWk, dbk, Kd, 1000, 1024, 4096, nullptr);
    sgemm<0><<<dim3(8, 8), blk>>>(protoD, dWv, dbv, Vd, 1000, 1024, 4096, nullptr);

    // attention (flash-style, per head)
    flash_attn<<<dim3(8, 16, 8), 64>>>(Qt, Kt, Vt, Ct, 1000);
    flash_attn<<<dim3(8, 16, 8), 64>>>(Qd, Kd, Vd, Cd, 1000);

    // gate MLP: H = relu(trend@W1a + detail@W1b + b1); G = sigmoid(H@W2 + b2)
    sgemm<0><<<dim3(8, 32), blk>>>(trend,  gW1,               gb1,     H, 4096, 1024, 1024, nullptr);
    sgemm<2><<<dim3(8, 32), blk>>>(detail, gW1 + 1024 * 1024, nullptr, H, 4096, 1024, 1024, nullptr);
    gate_kernel<<<512, 256>>>(H, gW2, gb2, G);

    // output projections + fused blend:
    // out = ctx_d@Wo_d + bo_d;  out = out + g*(ctx_t@Wo_t + bo_t - out)
    sgemm<0><<<dim3(32, 32), blk>>>(Cd, dWo, dbo, out, 4096, 4096, 1024, nullptr);
    sgemm<3><<<dim3(32, 32), blk>>>(Ct, tWo, tbo, out, 4096, 4096, 1024, G);

    (void)in_sizes; (void)n_in; (void)out_size;
}

// round 2
// speedup vs baseline: 1.5277x; 1.5277x over previous
#include <cuda_runtime.h>
#include <cstdint>

typedef unsigned long long u64;

// ---------------- packed fp32x2 helpers (sm_100+ fma.rn.f32x2) ----------------
__device__ __forceinline__ u64 pack2(float x, float y) {
    u64 r; asm("mov.b64 %0, {%1, %2};" : "=l"(r) : "f"(x), "f"(y)); return r;
}
__device__ __forceinline__ float2 unpack2(u64 v) {
    float2 r; asm("mov.b64 {%0, %1}, %2;" : "=f"(r.x), "=f"(r.y) : "l"(v)); return r;
}
__device__ __forceinline__ void fma2(u64& d, u64 a, u64 b) {
    asm("fma.rn.f32x2 %0, %1, %2, %0;" : "+l"(d) : "l"(a), "l"(b));
}
__device__ __forceinline__ u64 mul2(u64 a, u64 b) {
    u64 d; asm("mul.rn.f32x2 %0, %1, %2;" : "=l"(d) : "l"(a), "l"(b)); return d;
}

// ---------------- scratch (device globals: allocation-free) ----------------
__device__ float g_Qt[4096 * 1024];
__device__ float g_Qd[4096 * 1024];
__device__ float g_Kt[1024 * 1024];
__device__ float g_Vt[1024 * 1024];
__device__ float g_Kd[1024 * 1024];
__device__ float g_Vd[1024 * 1024];
__device__ float g_Ct[4096 * 1024];
__device__ float g_Cd[4096 * 1024];
__device__ float g_H [4096 * 1024];
__device__ float g_gate[4096];

// ---------------- multi-operand GEMM argument block ----------------
struct GArg {
    const float* A[4];
    const float* A2[4];   // second K-segment source (DUAL only)
    const float* B[4];
    const float* bias[4];
    float*       C[4];
    const float* gate;
    int M, N, K, Ksplit;  // Ksplit: k >= Ksplit reads A2 (DUAL)
};

// ---------------- tiled SGEMM 128x128x16, double-buffered, f32x2 core --------
// EPI 0: C = AB + bias
// EPI 1: C = relu(AB + bias)                  (with DUAL-A K concat)
// EPI 3: C = C + gate[r]*((AB + bias) - C)    (lerp blend)
template<int EPI, bool DUAL>
__global__ __launch_bounds__(256, 2)
void sgemm(GArg g)
{
    __shared__ __align__(16) float As[2][16][128];
    __shared__ __align__(16) float Bs[2][16][128];

    const int z = blockIdx.z;
    const float* __restrict__ A    = g.A[z];
    const float* __restrict__ A2   = g.A2[z];
    const float* __restrict__ B    = g.B[z];
    const float* __restrict__ bias = g.bias[z];
    float* __restrict__ C          = g.C[z];
    const int M = g.M, N = g.N, K = g.K, Ksp = g.Ksplit;
    const int lda = DUAL ? Ksp : K;

    const int tid  = threadIdx.x;
    const int row0 = blockIdx.y * 128;
    const int col0 = blockIdx.x * 128;
    const int tx   = tid & 15;
    const int ty   = tid >> 4;

    // A-tile loader mapping: 128 rows x 16 k, two float4 per thread
    const int aRow = tid >> 2;          // 0..63 (l adds 64)
    const int aK   = (tid & 3) * 4;
    // B-tile loader mapping: 16 k x 128 cols, two float4 per thread
    const int bRow = tid >> 5;          // 0..7 (l adds 8)
    const int bCol = (tid & 31) * 4;

    const bool av0 = (row0 + aRow)      < M;
    const bool av1 = (row0 + aRow + 64) < M;

    u64 acc[8][4] = {};   // [row i][col pair]: cols {tx*4+0..3, 64+tx*4+0..3}

    float4 aReg[2], bReg[2];

    auto load_stage = [&](int k0) {
        #pragma unroll
        for (int l = 0; l < 2; l++) {
            int kg = k0 + aK;
            const float* base = A;
            if (DUAL && kg >= Ksp) { base = A2; kg -= Ksp; }
            int r = row0 + aRow + l * 64;
            bool v = l ? av1 : av0;
            aReg[l] = v ? *(const float4*)(base + (size_t)r * lda + kg)
                        : make_float4(0.f, 0.f, 0.f, 0.f);
        }
        #pragma unroll
        for (int l = 0; l < 2; l++) {
            int br = k0 + bRow + l * 8;
            bReg[l] = *(const float4*)(B + (size_t)br * N + col0 + bCol);
        }
    };
    auto store_stage = [&](int buf) {
        #pragma unroll
        for (int l = 0; l < 2; l++) {
            int r = aRow + l * 64;
            As[buf][aK + 0][r] = aReg[l].x;
            As[buf][aK + 1][r] = aReg[l].y;
            As[buf][aK + 2][r] = aReg[l].z;
            As[buf][aK + 3][r] = aReg[l].w;
            *(float4*)&Bs[buf][bRow + l * 8][bCol] = bReg[l];
        }
    };

    load_stage(0);
    store_stage(0);
    __syncthreads();

    const int nst = K / 16;
    for (int s = 0; s < nst; s++) {
        const int buf = s & 1;
        if (s + 1 < nst) load_stage((s + 1) * 16);

        #pragma unroll
        for (int kk = 0; kk < 16; kk++) {
            float4 b0 = *(const float4*)&Bs[buf][kk][tx * 4];
            float4 b1 = *(const float4*)&Bs[buf][kk][64 + tx * 4];
            u64 b2[4] = { pack2(b0.x, b0.y), pack2(b0.z, b0.w),
                          pack2(b1.x, b1.y), pack2(b1.z, b1.w) };
            float4 a0 = *(const float4*)&As[buf][kk][ty * 8];
            float4 a1 = *(const float4*)&As[buf][kk][ty * 8 + 4];
            float avv[8] = { a0.x, a0.y, a0.z, a0.w, a1.x, a1.y, a1.z, a1.w };
            #pragma unroll
            for (int i = 0; i < 8; i++) {
                u64 ad = pack2(avv[i], avv[i]);
                fma2(acc[i][0], ad, b2[0]);
                fma2(acc[i][1], ad, b2[1]);
                fma2(acc[i][2], ad, b2[2]);
                fma2(acc[i][3], ad, b2[3]);
            }
        }

        if (s + 1 < nst) store_stage(buf ^ 1);
        __syncthreads();
    }

    // epilogue
    #pragma unroll
    for (int i = 0; i < 8; i++) {
        int r = row0 + ty * 8 + i;
        if (r >= M) continue;
        float gg = (EPI == 3) ? g.gate[r] : 0.f;
        #pragma unroll
        for (int grp = 0; grp < 2; grp++) {
            int c = col0 + grp * 64 + tx * 4;
            size_t idx = (size_t)r * N + c;
            float2 va = unpack2(acc[i][grp * 2 + 0]);
            float2 vb = unpack2(acc[i][grp * 2 + 1]);
            float s0 = va.x + bias[c + 0];
            float s1 = va.y + bias[c + 1];
            float s2 = vb.x + bias[c + 2];
            float s3 = vb.y + bias[c + 3];
            float4 o;
            if (EPI == 0) {
                o = make_float4(s0, s1, s2, s3);
            } else if (EPI == 1) {
                o = make_float4(fmaxf(s0, 0.f), fmaxf(s1, 0.f),
                                fmaxf(s2, 0.f), fmaxf(s3, 0.f));
            } else {
                float4 old = *(const float4*)(C + idx);
                o = make_float4(old.x + gg * (s0 - old.x),
                                old.y + gg * (s1 - old.y),
                                old.z + gg * (s2 - old.z),
                                old.w + gg * (s3 - old.w));
            }
            *(float4*)(C + idx) = o;
        }
    }
}

// ---------------- flash attention: 1 thread per query row, online softmax ----
struct FArg {
    const float* Q[2];
    const float* Kb[2];
    const float* Vb[2];
    float*       O[2];
};

__global__ __launch_bounds__(64)
void flash_attn(FArg f, int S)
{
    __shared__ __align__(16) u64 Ks[64 * 32];     // 16 KB
    __shared__ __align__(16) u64 Vs[64 * 32];     // 16 KB
    __shared__ float Ss[64 * 64];                 // 16 KB
    const int tid = threadIdx.x;
    const int h   = blockIdx.y;
    const int sel = blockIdx.z >> 3;
    const int b   = blockIdx.z & 7;
    const int row = b * 512 + blockIdx.x * 64 + tid;

    const float* __restrict__ Q  = f.Q[sel];
    const float* __restrict__ Kb = f.Kb[sel];
    const float* __restrict__ Vb = f.Vb[sel];
    float* __restrict__ O        = f.O[sel];

    const u64* qp = (const u64*)(Q + (size_t)row * 1024 + h * 64);
    u64 q2[32];
    #pragma unroll
    for (int i = 0; i < 32; i++) q2[i] = qp[i];

    u64 acc2[32] = {};
    float m = -1e30f, lsum = 0.f;
    const float scale = 0.125f;  // 1/sqrt(64)

    for (int s0 = 0; s0 < S; s0 += 64) {
        int jmax = S - s0; if (jmax > 64) jmax = 64;
        #pragma unroll
        for (int i = 0; i < 32; i++) {
            int idx = i * 64 + tid;
            int j = idx >> 5, e2 = idx & 31;
            int srow = s0 + j;
            u64 kv = 0, vv = 0;
            if (srow < S) {
                kv = ((const u64*)(Kb + (size_t)srow * 1024 + h * 64))[e2];
                vv = ((const u64*)(Vb + (size_t)srow * 1024 + h * 64))[e2];
            }
            Ks[idx] = kv; Vs[idx] = vv;
        }
        __syncthreads();

        float tmax = -1e30f;
        for (int j = 0; j < 64; j++) {
            float s;
            if (j < jmax) {
                u64 s2 = 0;
                const ulonglong2* kp = (const ulonglong2*)&Ks[j * 32];
                #pragma unroll
                for (int e = 0; e < 16; e++) {
                    ulonglong2 kv = kp[e];
                    fma2(s2, q2[e * 2],     kv.x);
                    fma2(s2, q2[e * 2 + 1], kv.y);
                }
                float2 sf = unpack2(s2);
                s = (sf.x + sf.y) * scale;
            } else {
                s = -1e30f;
            }
            tmax = fmaxf(tmax, s);
            Ss[j * 64 + tid] = s;
        }

        float mnew  = fmaxf(m, tmax);
        float alpha = __expf(m - mnew);
        lsum *= alpha;
        u64 a2 = pack2(alpha, alpha);
        #pragma unroll
        for (int e = 0; e < 32; e++) acc2[e] = mul2(acc2[e], a2);

        for (int j = 0; j < 64; j++) {
            float p = __expf(Ss[j * 64 + tid] - mnew);
            lsum += p;
            u64 p2 = pack2(p, p);
            const ulonglong2* vp = (const ulonglong2*)&Vs[j * 32];
            #pragma unroll
            for (int e = 0; e < 16; e++) {
                ulonglong2 vv = vp[e];
                fma2(acc2[e * 2],     p2, vv.x);
                fma2(acc2[e * 2 + 1], p2, vv.y);
            }
        }
        m = mnew;
        __syncthreads();
    }

    float inv = 1.f / lsum;
    float2* op = (float2*)(O + (size_t)row * 1024 + h * 64);
    #pragma unroll
    for (int e = 0; e < 32; e++) {
        float2 v = unpack2(acc2[e]);
        v.x *= inv; v.y *= inv;
        op[e] = v;
    }
}

// ---------------- gate: G[r] = sigmoid(H[r,:] . W2 + b2), one warp per row ----
__global__ __launch_bounds__(256)
void gate_kernel(const float* __restrict__ H, const float* __restrict__ W2,
                 const float* __restrict__ b2, float* __restrict__ G)
{
    int w = (blockIdx.x * blockDim.x + threadIdx.x) >> 5;
    int lane = threadIdx.x & 31;
    const float* hp = H + (size_t)w * 1024;
    float s = 0.f;
    #pragma unroll
    for (int i = 0; i < 32; i++) s += hp[lane + i * 32] * W2[lane + i * 32];
    #pragma unroll
    for (int o = 16; o; o >>= 1) s += __shfl_xor_sync(0xffffffffu, s, o);
    if (lane == 0) G[w] = 1.f / (1.f + __expf(-(s + b2[0])));
}

// ---------------- launch ----------------
extern "C" void kernel_launch(void* const* d_in, const int* in_sizes, int n_in,
                              void* d_out, int out_size)
{
    const float* trend  = (const float*)d_in[0];
    const float* detail = (const float*)d_in[1];
    const float* protoT = (const float*)d_in[2];
    const float* protoD = (const float*)d_in[3];
    const float* tWq = (const float*)d_in[4];  const float* tbq = (const float*)d_in[5];
    const float* tWk = (const float*)d_in[6];  const float* tbk = (const float*)d_in[7];
    const float* tWv = (const float*)d_in[8];  const float* tbv = (const float*)d_in[9];
    const float* tWo = (const float*)d_in[10]; const float* tbo = (const float*)d_in[11];
    const float* dWq = (const float*)d_in[12]; const float* dbq = (const float*)d_in[13];
    const float* dWk = (const float*)d_in[14]; const float* dbk = (const float*)d_in[15];
    const float* dWv = (const float*)d_in[16]; const float* dbv = (const float*)d_in[17];
    const float* dWo = (const float*)d_in[18]; const float* dbo = (const float*)d_in[19];
    const float* gW1 = (const float*)d_in[20]; const float* gb1 = (const float*)d_in[21];
    const float* gW2 = (const float*)d_in[22]; const float* gb2 = (const float*)d_in[23];
    float* out = (float*)d_out;

    float *Qt, *Qd, *Kt, *Vt, *Kd, *Vd, *Ct, *Cd, *H, *G;
    cudaGetSymbolAddress((void**)&Qt, g_Qt);
    cudaGetSymbolAddress((void**)&Qd, g_Qd);
    cudaGetSymbolAddress((void**)&Kt, g_Kt);
    cudaGetSymbolAddress((void**)&Vt, g_Vt);
    cudaGetSymbolAddress((void**)&Kd, g_Kd);
    cudaGetSymbolAddress((void**)&Vd, g_Vd);
    cudaGetSymbolAddress((void**)&Ct, g_Ct);
    cudaGetSymbolAddress((void**)&Cd, g_Cd);
    cudaGetSymbolAddress((void**)&H,  g_H);
    cudaGetSymbolAddress((void**)&G,  g_gate);

    // 1) Q projections, merged (z=2): (4096,1024) = emb @ Wq + bq
    {
        GArg a = {};
        a.A[0] = trend;  a.B[0] = tWq; a.bias[0] = tbq; a.C[0] = Qt;
        a.A[1] = detail; a.B[1] = dWq; a.bias[1] = dbq; a.C[1] = Qd;
        a.M = 4096; a.N = 1024; a.K = 1024; a.Ksplit = 0;
        sgemm<0, false><<<dim3(8, 32, 2), 256>>>(a);
    }
    // 2) K/V projections, merged (z=4): (1000,1024) = protos @ W + b
    {
        GArg a = {};
        a.A[0] = protoT; a.B[0] = tWk; a.bias[0] = tbk; a.C[0] = Kt;
        a.A[1] = protoT; a.B[1] = tWv; a.bias[1] = tbv; a.C[1] = Vt;
        a.A[2] = protoD; a.B[2] = dWk; a.bias[2] = dbk; a.C[2] = Kd;
        a.A[3] = protoD; a.B[3] = dWv; a.bias[3] = dbv; a.C[3] = Vd;
        a.M = 1000; a.N = 1024; a.K = 4096; a.Ksplit = 0;
        sgemm<0, false><<<dim3(8, 8, 4), 256>>>(a);
    }
    // 3) attention, both branches merged (z: sel*8 + batch)
    {
        FArg fa = {};
        fa.Q[0] = Qt; fa.Kb[0] = Kt; fa.Vb[0] = Vt; fa.O[0] = Ct;
        fa.Q[1] = Qd; fa.Kb[1] = Kd; fa.Vb[1] = Vd; fa.O[1] = Cd;
        flash_attn<<<dim3(8, 16, 16), 64>>>(fa, 1000);
    }
    // 4) gate MLP layer 1: H = relu([trend|detail] @ gW1 + gb1), dual-K
    {
        GArg a = {};
        a.A[0] = trend; a.A2[0] = detail; a.B[0] = gW1; a.bias[0] = gb1; a.C[0] = H;
        a.M = 4096; a.N = 1024; a.K = 2048; a.Ksplit = 1024;
        sgemm<1, true><<<dim3(8, 32, 1), 256>>>(a);
    }
    // 5) gate
    gate_kernel<<<512, 256>>>(H, gW2, gb2, G);

    // 6) output projections + fused blend
    {
        GArg a = {};
        a.A[0] = Cd; a.B[0] = dWo; a.bias[0] = dbo; a.C[0] = out;
        a.M = 4096; a.N = 4096; a.K = 1024; a.Ksplit = 0;
        sgemm<0, false><<<dim3(32, 32, 1), 256>>>(a);
    }
    {
        GArg a = {};
        a.A[0] = Ct; a.B[0] = tWo; a.bias[0] = tbo; a.C[0] = out; a.gate = G;
        a.M = 4096; a.N = 4096; a.K = 1024; a.Ksplit = 0;
        sgemm<3, false><<<dim3(32, 32, 1), 256>>>(a);
    }

    (void)in_sizes; (void)n_in; (void)out_size;
}